// round 10
// baseline (speedup 1.0000x reference)
#include <cuda_runtime.h>
#include <cuda_bf16.h>
#include <math.h>
#include <stdint.h>

#define B       4
#define HID     5120
#define QLORA   1536
#define NH      128
#define QD      192
#define NOPE    128
#define PE      64
#define KVL     512
#define VD      128
#define KVLEN   2048
#define CAT     576      // 512 (absorbed nope) + 64 (rope)
#define OCP_SEG 8        // K-split segments for o_c GEMM (256 each)
#define FCH     8        // i-chunks for final GEVM (2048 floats each)
#define SCALE   0.07216878364870323f  // 192^-0.5
#define LOG2_10000 13.28771237954945f

// ------------------- device scratch (no allocation allowed) -------------------
__device__ float g_qap[2 * B * QLORA];          // split-K partials of q_a
__device__ float g_qant[QLORA * B];             // rmsnormed q_a, transposed [c][b]
__device__ float g_q[B * NH * QD];              // q after w_q_b
__device__ float g_qcat[B * NH * CAT];          // [q_absorbed(512) | q_pe_roped(64)]
__device__ float g_kpe[B * KVLEN * PE];         // roped k_pe
__device__ float g_scores[B * NH * KVLEN];      // scores, then attn (in place)
__device__ float g_ocp[OCP_SEG * B * NH * KVL]; // o_c partials (deterministic K-split)
__device__ float g_oc[B * NH * KVL];            // o_c = attn @ ckv
__device__ float g_outvt[NH * VD * B];          // out_v transposed [i][b] (float4/i)
__device__ float g_finp[FCH * B * HID];         // final GEVM split-K partials

// ------------------- tf32 helpers -------------------
__device__ __forceinline__ uint32_t f2tf(float f) {
    uint32_t u;
    asm("cvt.rna.tf32.f32 %0, %1;" : "=r"(u) : "f"(f));
    return u;
}
__device__ __forceinline__ void mma_tf32(float* c,
                                         uint32_t a0, uint32_t a1, uint32_t a2, uint32_t a3,
                                         uint32_t b0, uint32_t b1) {
    asm volatile(
        "mma.sync.aligned.m16n8k8.row.col.f32.tf32.tf32.f32 "
        "{%0,%1,%2,%3}, {%4,%5,%6,%7}, {%8,%9}, {%0,%1,%2,%3};"
        : "+f"(c[0]), "+f"(c[1]), "+f"(c[2]), "+f"(c[3])
        : "r"(a0), "r"(a1), "r"(a2), "r"(a3), "r"(b0), "r"(b1));
}

// ------------------- kernel 1: q_a partials = hidden @ w_q_a.T (split-K) -------------------
__global__ void __launch_bounds__(256) k_qa(const float* __restrict__ hidden,
                                            const float* __restrict__ wqa) {
    int warp = threadIdx.x >> 5, lane = threadIdx.x & 31;
    int row = blockIdx.x * 8 + warp;
    int s = blockIdx.y;  // 0,1 halves of HID
    const float4* w4 = reinterpret_cast<const float4*>(wqa + (size_t)row * HID) + s * 640;
    const float4* h4 = reinterpret_cast<const float4*>(hidden);
    float acc[B] = {0.f, 0.f, 0.f, 0.f};
#pragma unroll 4
    for (int t = lane; t < 640; t += 32) {
        float4 w = w4[t];
#pragma unroll
        for (int b = 0; b < B; b++) {
            float4 h = h4[b * 1280 + s * 640 + t];
            acc[b] += w.x * h.x + w.y * h.y + w.z * h.z + w.w * h.w;
        }
    }
#pragma unroll
    for (int b = 0; b < B; b++)
#pragma unroll
        for (int o = 16; o; o >>= 1) acc[b] += __shfl_xor_sync(0xffffffffu, acc[b], o);
    if (lane == 0) {
#pragma unroll
        for (int b = 0; b < B; b++) g_qap[s * (B * QLORA) + b * QLORA + row] = acc[b];
    }
}

// ------------------- kernel 2: rmsnorm (sums split-K partials), write transposed -------------------
__global__ void __launch_bounds__(256) k_rms(const float* __restrict__ wln) {
    int b = blockIdx.x, t = threadIdx.x;
    const float* x0 = g_qap + b * QLORA;
    const float* x1 = g_qap + B * QLORA + b * QLORA;
    float s = 0.f;
    for (int i = t; i < QLORA; i += 256) { float v = x0[i] + x1[i]; s += v * v; }
    __shared__ float red[8];
#pragma unroll
    for (int o = 16; o; o >>= 1) s += __shfl_xor_sync(0xffffffffu, s, o);
    if ((t & 31) == 0) red[t >> 5] = s;
    __syncthreads();
    float tot = 0.f;
#pragma unroll
    for (int w = 0; w < 8; w++) tot += red[w];
    float r = rsqrtf(tot / (float)QLORA + 1e-6f);
    for (int i = t; i < QLORA; i += 256) {
        float v = x0[i] + x1[i];
        g_qant[i * B + b] = wln[i] * v * r;
    }
}

// ------------------- kernel 3: q = q_a_n @ w_q_b.T (warp = 2 rows, shared smem reads) ----
__global__ void __launch_bounds__(256) k_qb(const float* __restrict__ wqb) {
    __shared__ __align__(16) float sh[QLORA * B];  // 24 KB, [c][b]
    int t = threadIdx.x;
    for (int i = t; i < QLORA * B; i += 256) sh[i] = g_qant[i];
    __syncthreads();
    int warp = t >> 5, lane = t & 31;
    int row = blockIdx.x * 16 + warp * 2;
    const float4* wA = reinterpret_cast<const float4*>(wqb + (size_t)row * QLORA);
    const float4* wB = reinterpret_cast<const float4*>(wqb + (size_t)(row + 1) * QLORA);
    const float4* s4 = reinterpret_cast<const float4*>(sh);
    float acc0[B] = {0.f, 0.f, 0.f, 0.f};
    float acc1[B] = {0.f, 0.f, 0.f, 0.f};
#pragma unroll
    for (int r = 0; r < 12; r++) {
        int q = lane + 32 * r;
        float4 w0 = wA[q], w1 = wB[q];
        float4 a = s4[q * 4 + 0], bb = s4[q * 4 + 1];
        float4 c = s4[q * 4 + 2], d = s4[q * 4 + 3];
        acc0[0] += w0.x * a.x + w0.y * bb.x + w0.z * c.x + w0.w * d.x;
        acc0[1] += w0.x * a.y + w0.y * bb.y + w0.z * c.y + w0.w * d.y;
        acc0[2] += w0.x * a.z + w0.y * bb.z + w0.z * c.z + w0.w * d.z;
        acc0[3] += w0.x * a.w + w0.y * bb.w + w0.z * c.w + w0.w * d.w;
        acc1[0] += w1.x * a.x + w1.y * bb.x + w1.z * c.x + w1.w * d.x;
        acc1[1] += w1.x * a.y + w1.y * bb.y + w1.z * c.y + w1.w * d.y;
        acc1[2] += w1.x * a.z + w1.y * bb.z + w1.z * c.z + w1.w * d.z;
        acc1[3] += w1.x * a.w + w1.y * bb.w + w1.z * c.w + w1.w * d.w;
    }
#pragma unroll
    for (int b = 0; b < B; b++) {
#pragma unroll
        for (int o = 16; o; o >>= 1) {
            acc0[b] += __shfl_xor_sync(0xffffffffu, acc0[b], o);
            acc1[b] += __shfl_xor_sync(0xffffffffu, acc1[b], o);
        }
    }
    if (lane == 0) {
#pragma unroll
        for (int b = 0; b < B; b++) {
            g_q[b * (NH * QD) + row] = acc0[b];
            g_q[b * (NH * QD) + row + 1] = acc1[b];
        }
    }
}

// ------------- kernel 4: q_abs[b,h,:] = q_nope[b,h,:] @ W_uk[h]  + rope(q_pe) -------------
// grid (NH, 8): (head, col eighth of 16 float4). block 256 = 16 float4-cols x 16 d-groups.
__global__ void __launch_bounds__(256) k_absorb(const float* __restrict__ wkvb) {
    int h = blockIdx.x, zz = blockIdx.y;
    int t = threadIdx.x;
    int tx = t & 15, ty = t >> 4;      // 16 cols x 16 d-groups (8 rows each)
    int col4 = zz * 16 + tx;           // float4 column in [0,128)
    __shared__ float qn[B * NOPE];     // [b][d]
    __shared__ float4 red[16][16][B];  // 16 KB
    for (int idx = t; idx < B * NOPE; idx += 256) {
        int b = idx >> 7, d = idx & 127;
        qn[idx] = g_q[b * (NH * QD) + h * QD + d];
    }
    __syncthreads();
    const float4* w4 = reinterpret_cast<const float4*>(wkvb) + (size_t)h * 256 * 128;
    float4 acc[B];
#pragma unroll
    for (int b = 0; b < B; b++) acc[b] = make_float4(0.f, 0.f, 0.f, 0.f);
#pragma unroll
    for (int d = 0; d < 8; d++) {
        float4 w = w4[(size_t)(ty * 8 + d) * 128 + col4];
#pragma unroll
        for (int b = 0; b < B; b++) {
            float q = qn[b * NOPE + ty * 8 + d];
            acc[b].x += q * w.x; acc[b].y += q * w.y;
            acc[b].z += q * w.z; acc[b].w += q * w.w;
        }
    }
#pragma unroll
    for (int b = 0; b < B; b++) red[ty][tx][b] = acc[b];
    __syncthreads();
    // 64 threads do the reduce: t = b*16 + tx
    if (t < 64) {
        int b = t >> 4, txx = t & 15;
        float4 s = red[0][txx][b];
#pragma unroll
        for (int g = 1; g < 16; g++) {
            float4 r = red[g][txx][b];
            s.x += r.x; s.y += r.y; s.z += r.z; s.w += r.w;
        }
        *reinterpret_cast<float4*>(&g_qcat[((size_t)(b * NH) + h) * CAT + (zz * 16 + txx) * 4]) = s;
    }
    // rope q_pe at position kv_len-1 = 2047 (done once per head, by zz==7 block)
    if (zz == 7 && t >= 128 && t < 256) {
        int tt = t - 128;
        int b = tt >> 5, j = tt & 31;
        float inv = exp2f(-(float)j * (LOG2_10000 / 32.f));
        float s, cc;
        sincosf(2047.0f * inv, &s, &cc);
        float xr = g_q[b * (NH * QD) + h * QD + NOPE + 2 * j];
        float xi = g_q[b * (NH * QD) + h * QD + NOPE + 2 * j + 1];
        g_qcat[((size_t)(b * NH) + h) * CAT + 512 + 2 * j]     = xr * cc - xi * s;
        g_qcat[((size_t)(b * NH) + h) * CAT + 512 + 2 * j + 1] = xr * s + xi * cc;
    }
}

// ------------------- kernel 5: rope k_pe for all positions (fp32) -------------------
__global__ void __launch_bounds__(256) k_ropek(const float* __restrict__ kpe) {
    int idx = blockIdx.x * 256 + threadIdx.x;  // < B*KVLEN*32 = 262144
    int j = idx & 31;
    int k = (idx >> 5) & (KVLEN - 1);
    int b = idx >> 16;
    float inv = exp2f(-(float)j * (LOG2_10000 / 32.f));
    float s, c;
    sincosf((float)k * inv, &s, &c);
    size_t base = ((size_t)(b * KVLEN) + k) * PE + 2 * j;
    float2 x = *reinterpret_cast<const float2*>(&kpe[base]);
    float2 o;
    o.x = x.x * c - x.y * s;
    o.y = x.x * s + x.y * c;
    *reinterpret_cast<float2*>(&g_kpe[base]) = o;
}

// ------------------- kernel 6: scores = qcat @ [ckv|kpe]^T * scale  (tf32 mma) -----
// grid (64 ktiles of 32, B); block 256 = 8 warps (4 m-groups x 2 n-groups)
// block tile: 128h x 32k; K-dim CAT staged in 18 chunks of 32
__global__ void __launch_bounds__(256) k_scores(const float* __restrict__ ckv) {
    __shared__ uint32_t A_sh[128 * 36];  // qcat chunk [h][c], stride 36 (18 KB)
    __shared__ uint32_t B_sh[32 * 36];   // kv chunk [k][c], stride 36 (4.5 KB)
    int b = blockIdx.y, k0 = blockIdx.x * 32;
    int t = threadIdx.x, w = t >> 5, lane = t & 31;
    int mw = w & 3, nw = w >> 2;
    int lq = lane >> 2, lr = lane & 3;   // groupID, threadID_in_group
    float acc[2][2][4];
#pragma unroll
    for (int mt = 0; mt < 2; mt++)
#pragma unroll
        for (int nt = 0; nt < 2; nt++)
#pragma unroll
            for (int i = 0; i < 4; i++) acc[mt][nt][i] = 0.f;

    for (int cc0 = 0; cc0 < CAT; cc0 += 32) {
        // stage A: qcat[b][0:128][cc0:cc0+32] -> tf32
#pragma unroll
        for (int r = 0; r < 16; r++) {
            int idx = r * 256 + t;
            int h = idx >> 5, c = idx & 31;
            A_sh[h * 36 + c] = f2tf(g_qcat[((size_t)(b << 7) + h) * CAT + cc0 + c]);
        }
        // stage B: kv rows k0..k0+32, cols cc0..cc0+32
#pragma unroll
        for (int r = 0; r < 4; r++) {
            int idx = r * 256 + t;
            int k = idx >> 5, c = idx & 31;
            float v = (cc0 < 512)
                ? ckv[((size_t)(b * KVLEN) + k0 + k) * KVL + cc0 + c]
                : g_kpe[((size_t)(b * KVLEN) + k0 + k) * PE + (cc0 - 512) + c];
            B_sh[k * 36 + c] = f2tf(v);
        }
        __syncthreads();
#pragma unroll
        for (int ks = 0; ks < 4; ks++) {
            int c = ks * 8;
            uint32_t a[2][4];
#pragma unroll
            for (int mt = 0; mt < 2; mt++) {
                int m0 = mw * 32 + mt * 16;
                a[mt][0] = A_sh[(m0 + lq) * 36 + c + lr];
                a[mt][1] = A_sh[(m0 + 8 + lq) * 36 + c + lr];
                a[mt][2] = A_sh[(m0 + lq) * 36 + c + 4 + lr];
                a[mt][3] = A_sh[(m0 + 8 + lq) * 36 + c + 4 + lr];
            }
#pragma unroll
            for (int nt = 0; nt < 2; nt++) {
                int n0 = nw * 16 + nt * 8;
                uint32_t b0 = B_sh[(n0 + lq) * 36 + c + lr];
                uint32_t b1 = B_sh[(n0 + lq) * 36 + c + 4 + lr];
                mma_tf32(acc[0][nt], a[0][0], a[0][1], a[0][2], a[0][3], b0, b1);
                mma_tf32(acc[1][nt], a[1][0], a[1][1], a[1][2], a[1][3], b0, b1);
            }
        }
        __syncthreads();
    }
    // writeback scaled scores
#pragma unroll
    for (int mt = 0; mt < 2; mt++) {
#pragma unroll
        for (int nt = 0; nt < 2; nt++) {
            int m0 = mw * 32 + mt * 16;
            int n0 = nw * 16 + nt * 8;
            int row = m0 + lq;
            int col = k0 + n0 + 2 * lr;
            float* base0 = &g_scores[((size_t)(b << 7) + row) * KVLEN + col];
            *reinterpret_cast<float2*>(base0) =
                make_float2(acc[mt][nt][0] * SCALE, acc[mt][nt][1] * SCALE);
            float* base1 = &g_scores[((size_t)(b << 7) + row + 8) * KVLEN + col];
            *reinterpret_cast<float2*>(base1) =
                make_float2(acc[mt][nt][2] * SCALE, acc[mt][nt][3] * SCALE);
        }
    }
}

// ------------------- kernel 7: softmax over k (in place) -------------------
__global__ void __launch_bounds__(256) k_softmax() {
    int bh = blockIdx.x, t = threadIdx.x;
    float* row = g_scores + (size_t)bh * KVLEN;
    __shared__ float redm[8], reds[8];
    float m = -1e30f;
    for (int i = t; i < KVLEN; i += 256) m = fmaxf(m, row[i]);
#pragma unroll
    for (int o = 16; o; o >>= 1) m = fmaxf(m, __shfl_xor_sync(0xffffffffu, m, o));
    if ((t & 31) == 0) redm[t >> 5] = m;
    __syncthreads();
    m = redm[0];
#pragma unroll
    for (int w = 1; w < 8; w++) m = fmaxf(m, redm[w]);
    float s = 0.f;
    for (int i = t; i < KVLEN; i += 256) {
        float e = expf(row[i] - m);
        row[i] = e;
        s += e;
    }
#pragma unroll
    for (int o = 16; o; o >>= 1) s += __shfl_xor_sync(0xffffffffu, s, o);
    if ((t & 31) == 0) reds[t >> 5] = s;
    __syncthreads();
    float tot = 0.f;
#pragma unroll
    for (int w = 0; w < 8; w++) tot += reds[w];
    float inv = 1.0f / tot;
    for (int i = t; i < KVLEN; i += 256) row[i] *= inv;
}

// ------------------- kernel 8: o_c partials = attn @ ckv (tf32 mma, K-split) -----
// grid (8 ctiles of 64, 8 ksegs of 256, B); block 256 = 8 warps (4 m x 2 n)
// block tile: 128h x 64c; K staged in 8 chunks of 32
__global__ void __launch_bounds__(256) k_oc(const float* __restrict__ ckv) {
    __shared__ uint32_t A_sh[128 * 36];   // attn chunk [h][k], stride 36 (18 KB)
    __shared__ uint32_t B_sh[32 * 72];    // ckv chunk [k][c], stride 72 (9 KB)
    int b = blockIdx.z, ks = blockIdx.y, c0 = blockIdx.x * 64;
    int k0b = ks * 256;
    int t = threadIdx.x, w = t >> 5, lane = t & 31;
    int mw = w & 3, nw = w >> 2;
    int lq = lane >> 2, lr = lane & 3;
    float acc[2][4][4];
#pragma unroll
    for (int mt = 0; mt < 2; mt++)
#pragma unroll
        for (int nt = 0; nt < 4; nt++)
#pragma unroll
            for (int i = 0; i < 4; i++) acc[mt][nt][i] = 0.f;

    for (int kc0 = 0; kc0 < 256; kc0 += 32) {
        int k0 = k0b + kc0;
        // stage A: attn[b][0:128][k0:k0+32]
#pragma unroll
        for (int r = 0; r < 16; r++) {
            int idx = r * 256 + t;
            int h = idx >> 5, k = idx & 31;
            A_sh[h * 36 + k] = f2tf(g_scores[((size_t)(b << 7) + h) * KVLEN + k0 + k]);
        }
        // stage B: ckv[b][k0:k0+32][c0:c0+64]
#pragma unroll
        for (int r = 0; r < 8; r++) {
            int idx = r * 256 + t;
            int k = idx >> 6, c = idx & 63;
            B_sh[k * 72 + c] = f2tf(ckv[((size_t)(b * KVLEN) + k0 + k) * KVL + c0 + c]);
        }
        __syncthreads();
#pragma unroll
        for (int kk = 0; kk < 32; kk += 8) {
            uint32_t a[2][4];
#pragma unroll
            for (int mt = 0; mt < 2; mt++) {
                int m0 = mw * 32 + mt * 16;
                a[mt][0] = A_sh[(m0 + lq) * 36 + kk + lr];
                a[mt][1] = A_sh[(m0 + 8 + lq) * 36 + kk + lr];
                a[mt][2] = A_sh[(m0 + lq) * 36 + kk + 4 + lr];
                a[mt][3] = A_sh[(m0 + 8 + lq) * 36 + kk + 4 + lr];
            }
#pragma unroll
            for (int nt = 0; nt < 4; nt++) {
                int n0 = nw * 32 + nt * 8;
                uint32_t b0 = B_sh[(kk + lr) * 72 + n0 + lq];
                uint32_t b1 = B_sh[(kk + 4 + lr) * 72 + n0 + lq];
                mma_tf32(acc[0][nt], a[0][0], a[0][1], a[0][2], a[0][3], b0, b1);
                mma_tf32(acc[1][nt], a[1][0], a[1][1], a[1][2], a[1][3], b0, b1);
            }
        }
        __syncthreads();
    }
    float* dst = g_ocp + (size_t)ks * (B * NH * KVL);
#pragma unroll
    for (int mt = 0; mt < 2; mt++) {
#pragma unroll
        for (int nt = 0; nt < 4; nt++) {
            int m0 = mw * 32 + mt * 16;
            int n0 = nw * 32 + nt * 8;
            int row = m0 + lq;
            int col = c0 + n0 + 2 * lr;
            *reinterpret_cast<float2*>(&dst[((size_t)(b << 7) + row) * KVL + col]) =
                make_float2(acc[mt][nt][0], acc[mt][nt][1]);
            *reinterpret_cast<float2*>(&dst[((size_t)(b << 7) + row + 8) * KVL + col]) =
                make_float2(acc[mt][nt][2], acc[mt][nt][3]);
        }
    }
}

// ------------------- kernel 9: reduce K-split partials -------------------
__global__ void __launch_bounds__(256) k_ocred() {
    int i = blockIdx.x * 256 + threadIdx.x;  // < B*NH*KVL = 262144
    float s = 0.f;
#pragma unroll
    for (int p = 0; p < OCP_SEG; p++) s += g_ocp[(size_t)p * (B * NH * KVL) + i];
    g_oc[i] = s;
}

// ------------------- kernel 10: out_v[b,h,:] = o_c[b,h,:] @ W_uv[h]^T -------------------
// grid NH*8: (h, dv-eighth of 16); warp computes 2 rows
__global__ void __launch_bounds__(256) k_outv(const float* __restrict__ wkvb) {
    int h = blockIdx.x >> 3, q = blockIdx.x & 7;
    int t = threadIdx.x;
    __shared__ __align__(16) float sh[KVL * B];  // [c][b], 8 KB
    for (int idx = t; idx < KVL * B; idx += 256) {
        int b = idx >> 9, c = idx & 511;
        sh[c * 4 + b] = g_oc[((size_t)(b << 7) + h) * KVL + c];
    }
    __syncthreads();
    int warp = t >> 5, lane = t & 31;
    const float4* sh4 = reinterpret_cast<const float4*>(sh);
    for (int r = 0; r < 2; r++) {
        int dv = q * 16 + warp * 2 + r;
        const float4* w4 = reinterpret_cast<const float4*>(wkvb + ((size_t)(h * 256 + 128 + dv)) * KVL);
        float acc[4] = {0.f, 0.f, 0.f, 0.f};
#pragma unroll
        for (int t4 = lane; t4 < 128; t4 += 32) {
            float4 w = w4[t4];
            float4 o0 = sh4[t4 * 4 + 0], o1 = sh4[t4 * 4 + 1];
            float4 o2 = sh4[t4 * 4 + 2], o3 = sh4[t4 * 4 + 3];
            acc[0] += w.x * o0.x + w.y * o1.x + w.z * o2.x + w.w * o3.x;
            acc[1] += w.x * o0.y + w.y * o1.y + w.z * o2.y + w.w * o3.y;
            acc[2] += w.x * o0.z + w.y * o1.z + w.z * o2.z + w.w * o3.z;
            acc[3] += w.x * o0.w + w.y * o1.w + w.z * o2.w + w.w * o3.w;
        }
#pragma unroll
        for (int b = 0; b < B; b++)
#pragma unroll
            for (int o = 16; o; o >>= 1) acc[b] += __shfl_xor_sync(0xffffffffu, acc[b], o);
        if (lane == 0)
            *reinterpret_cast<float4*>(&g_outvt[(h * VD + dv) * 4]) =
                make_float4(acc[0], acc[1], acc[2], acc[3]);
    }
}

// ------------------- kernel 11: final GEVM partials (split-K, warp = 2 rows) -----
// grid (HID/16, FCH); block 256; warp handles 2 rows sharing smem reads
__global__ void __launch_bounds__(256) k_final(const float* __restrict__ wo) {
    __shared__ float sv[B][2048];  // 32 KB: ov chunk as 4 batch planes
    int j0 = blockIdx.x * 16;
    int c0 = blockIdx.y * 2048;    // i offset of this chunk
    int t = threadIdx.x;
    const float4* ov4 = reinterpret_cast<const float4*>(g_outvt);
    for (int li = t; li < 2048; li += 256) {
        float4 v = ov4[c0 + li];   // all 4 batches for element c0+li
        sv[0][li] = v.x; sv[1][li] = v.y; sv[2][li] = v.z; sv[3][li] = v.w;
    }
    __syncthreads();
    int warp = t >> 5, lane = t & 31;
    int j = j0 + warp * 2;
    const float4* wjA = reinterpret_cast<const float4*>(wo + (size_t)j * (NH * VD)) + (c0 >> 2);
    const float4* wjB = reinterpret_cast<const float4*>(wo + (size_t)(j + 1) * (NH * VD)) + (c0 >> 2);
    float a0 = 0.f, a1 = 0.f, a2 = 0.f, a3 = 0.f;
    float b0 = 0.f, b1 = 0.f, b2 = 0.f, b3 = 0.f;
#pragma unroll
    for (int r = 0; r < 16; r++) {
        int l4 = lane + 32 * r;    // contiguous across lanes -> conflict-free LDS.128
        float4 wA = wjA[l4];
        float4 wB = wjB[l4];
        float4 s0 = *reinterpret_cast<const float4*>(&sv[0][l4 * 4]);
        float4 s1 = *reinterpret_cast<const float4*>(&sv[1][l4 * 4]);
        float4 s2 = *reinterpret_cast<const float4*>(&sv[2][l4 * 4]);
        float4 s3 = *reinterpret_cast<const float4*>(&sv[3][l4 * 4]);
        a0 += wA.x * s0.x + wA.y * s0.y + wA.z * s0.z + wA.w * s0.w;
        a1 += wA.x * s1.x + wA.y * s1.y + wA.z * s1.z + wA.w * s1.w;
        a2 += wA.x * s2.x + wA.y * s2.y + wA.z * s2.z + wA.w * s2.w;
        a3 += wA.x * s3.x + wA.y * s3.y + wA.z * s3.z + wA.w * s3.w;
        b0 += wB.x * s0.x + wB.y * s0.y + wB.z * s0.z + wB.w * s0.w;
        b1 += wB.x * s1.x + wB.y * s1.y + wB.z * s1.z + wB.w * s1.w;
        b2 += wB.x * s2.x + wB.y * s2.y + wB.z * s2.z + wB.w * s2.w;
        b3 += wB.x * s3.x + wB.y * s3.y + wB.z * s3.z + wB.w * s3.w;
    }
#pragma unroll
    for (int o = 16; o; o >>= 1) {
        a0 += __shfl_xor_sync(0xffffffffu, a0, o);
        a1 += __shfl_xor_sync(0xffffffffu, a1, o);
        a2 += __shfl_xor_sync(0xffffffffu, a2, o);
        a3 += __shfl_xor_sync(0xffffffffu, a3, o);
        b0 += __shfl_xor_sync(0xffffffffu, b0, o);
        b1 += __shfl_xor_sync(0xffffffffu, b1, o);
        b2 += __shfl_xor_sync(0xffffffffu, b2, o);
        b3 += __shfl_xor_sync(0xffffffffu, b3, o);
    }
    if (lane == 0) {
        size_t base = (size_t)blockIdx.y * (B * HID) + j;
        g_finp[base + 0 * HID] = a0;
        g_finp[base + 1 * HID] = a1;
        g_finp[base + 2 * HID] = a2;
        g_finp[base + 3 * HID] = a3;
        g_finp[base + 0 * HID + 1] = b0;
        g_finp[base + 1 * HID + 1] = b1;
        g_finp[base + 2 * HID + 1] = b2;
        g_finp[base + 3 * HID + 1] = b3;
    }
}

// ------------------- kernel 12: reduce final partials -------------------
__global__ void __launch_bounds__(256) k_fred(float* __restrict__ out) {
    int i = blockIdx.x * 256 + threadIdx.x;  // < B*HID = 20480
    float s = 0.f;
#pragma unroll
    for (int ch = 0; ch < FCH; ch++) s += g_finp[ch * (B * HID) + i];
    out[i] = s;
}

// ------------------- launch -------------------
extern "C" void kernel_launch(void* const* d_in, const int* in_sizes, int n_in,
                              void* d_out, int out_size) {
    const float* hidden = (const float*)d_in[0];
    const float* ckv    = (const float*)d_in[1];
    const float* kpe    = (const float*)d_in[2];
    const float* wqa    = (const float*)d_in[3];
    const float* wln    = (const float*)d_in[4];
    const float* wqb    = (const float*)d_in[5];
    const float* wkvb   = (const float*)d_in[6];
    const float* wo     = (const float*)d_in[7];
    float* out = (float*)d_out;

    k_qa<<<dim3(QLORA / 8, 2), 256>>>(hidden, wqa);
    k_rms<<<B, 256>>>(wln);
    k_qb<<<(NH * QD) / 16, 256>>>(wqb);
    k_absorb<<<dim3(NH, 8), 256>>>(wkvb);
    k_ropek<<<(B * KVLEN * 32) / 256, 256>>>(kpe);
    k_scores<<<dim3(KVLEN / 32, B), 256>>>(ckv);
    k_softmax<<<B * NH, 256>>>();
    k_oc<<<dim3(KVL / 64, OCP_SEG, B), 256>>>(ckv);
    k_ocred<<<(B * NH * KVL) / 256, 256>>>();
    k_outv<<<NH * 8, 256>>>(wkvb);
    k_final<<<dim3(HID / 16, FCH), 256>>>(wo);
    k_fred<<<(B * HID) / 256, 256>>>(out);
}

// round 11
// speedup vs baseline: 1.2835x; 1.2835x over previous
#include <cuda_runtime.h>
#include <cuda_bf16.h>
#include <math.h>
#include <stdint.h>

#define B       4
#define HID     5120
#define QLORA   1536
#define NH      128
#define QD      192
#define NOPE    128
#define PE      64
#define KVL     512
#define VD      128
#define KVLEN   2048
#define CAT     576      // 512 (absorbed nope) + 64 (rope)
#define OCP_SEG 8        // K-split segments for o_c GEMM (256 each)
#define FCH     8        // i-chunks for final GEVM (2048 floats each)
#define SCALE   0.07216878364870323f  // 192^-0.5
#define LOG2_10000 13.28771237954945f

// ------------------- device scratch (no allocation allowed) -------------------
__device__ float g_qap[2 * B * QLORA];          // split-K partials of q_a
__device__ float g_qant[QLORA * B];             // rmsnormed q_a, transposed [c][b]
__device__ float g_q[B * NH * QD];              // q after w_q_b
__device__ float g_qcat[B * NH * CAT];          // [q_absorbed(512) | q_pe_roped(64)]
__device__ float g_kpe[B * KVLEN * PE];         // roped k_pe
__device__ float g_scores[B * NH * KVLEN];      // scores, then attn (in place)
__device__ float g_ocp[OCP_SEG * B * NH * KVL]; // o_c partials (deterministic K-split)
__device__ float g_oc[B * NH * KVL];            // o_c = attn @ ckv
__device__ float g_outvt[NH * VD * B];          // out_v transposed [i][b] (float4/i)
__device__ float g_finp[FCH * B * HID];         // final GEVM split-K partials

// ------------------- tf32 helpers -------------------
__device__ __forceinline__ uint32_t f2tf(float f) {
    uint32_t u;
    asm("cvt.rna.tf32.f32 %0, %1;" : "=r"(u) : "f"(f));
    return u;
}
__device__ __forceinline__ void mma_tf32(float* c,
                                         uint32_t a0, uint32_t a1, uint32_t a2, uint32_t a3,
                                         uint32_t b0, uint32_t b1) {
    asm volatile(
        "mma.sync.aligned.m16n8k8.row.col.f32.tf32.tf32.f32 "
        "{%0,%1,%2,%3}, {%4,%5,%6,%7}, {%8,%9}, {%0,%1,%2,%3};"
        : "+f"(c[0]), "+f"(c[1]), "+f"(c[2]), "+f"(c[3])
        : "r"(a0), "r"(a1), "r"(a2), "r"(a3), "r"(b0), "r"(b1));
}

// ------------------- kernel 1: q_a partials = hidden @ w_q_a.T (split-K) -------------------
__global__ void __launch_bounds__(256) k_qa(const float* __restrict__ hidden,
                                            const float* __restrict__ wqa) {
    int warp = threadIdx.x >> 5, lane = threadIdx.x & 31;
    int row = blockIdx.x * 8 + warp;
    int s = blockIdx.y;  // 0,1 halves of HID
    const float4* w4 = reinterpret_cast<const float4*>(wqa + (size_t)row * HID) + s * 640;
    const float4* h4 = reinterpret_cast<const float4*>(hidden);
    float acc[B] = {0.f, 0.f, 0.f, 0.f};
#pragma unroll 4
    for (int t = lane; t < 640; t += 32) {
        float4 w = w4[t];
#pragma unroll
        for (int b = 0; b < B; b++) {
            float4 h = h4[b * 1280 + s * 640 + t];
            acc[b] += w.x * h.x + w.y * h.y + w.z * h.z + w.w * h.w;
        }
    }
#pragma unroll
    for (int b = 0; b < B; b++)
#pragma unroll
        for (int o = 16; o; o >>= 1) acc[b] += __shfl_xor_sync(0xffffffffu, acc[b], o);
    if (lane == 0) {
#pragma unroll
        for (int b = 0; b < B; b++) g_qap[s * (B * QLORA) + b * QLORA + row] = acc[b];
    }
}

// ------------------- kernel 2: rmsnorm (sums split-K partials), write transposed -------------------
__global__ void __launch_bounds__(256) k_rms(const float* __restrict__ wln) {
    int b = blockIdx.x, t = threadIdx.x;
    const float* x0 = g_qap + b * QLORA;
    const float* x1 = g_qap + B * QLORA + b * QLORA;
    float s = 0.f;
    for (int i = t; i < QLORA; i += 256) { float v = x0[i] + x1[i]; s += v * v; }
    __shared__ float red[8];
#pragma unroll
    for (int o = 16; o; o >>= 1) s += __shfl_xor_sync(0xffffffffu, s, o);
    if ((t & 31) == 0) red[t >> 5] = s;
    __syncthreads();
    float tot = 0.f;
#pragma unroll
    for (int w = 0; w < 8; w++) tot += red[w];
    float r = rsqrtf(tot / (float)QLORA + 1e-6f);
    for (int i = t; i < QLORA; i += 256) {
        float v = x0[i] + x1[i];
        g_qant[i * B + b] = wln[i] * v * r;
    }
}

// ------------------- kernel 3: q = q_a_n @ w_q_b.T (warp = 2 rows, shared smem reads) ----
__global__ void __launch_bounds__(256) k_qb(const float* __restrict__ wqb) {
    __shared__ __align__(16) float sh[QLORA * B];  // 24 KB, [c][b]
    int t = threadIdx.x;
    for (int i = t; i < QLORA * B; i += 256) sh[i] = g_qant[i];
    __syncthreads();
    int warp = t >> 5, lane = t & 31;
    int row = blockIdx.x * 16 + warp * 2;
    const float4* wA = reinterpret_cast<const float4*>(wqb + (size_t)row * QLORA);
    const float4* wB = reinterpret_cast<const float4*>(wqb + (size_t)(row + 1) * QLORA);
    const float4* s4 = reinterpret_cast<const float4*>(sh);
    float acc0[B] = {0.f, 0.f, 0.f, 0.f};
    float acc1[B] = {0.f, 0.f, 0.f, 0.f};
#pragma unroll
    for (int r = 0; r < 12; r++) {
        int q = lane + 32 * r;
        float4 w0 = wA[q], w1 = wB[q];
        float4 a = s4[q * 4 + 0], bb = s4[q * 4 + 1];
        float4 c = s4[q * 4 + 2], d = s4[q * 4 + 3];
        acc0[0] += w0.x * a.x + w0.y * bb.x + w0.z * c.x + w0.w * d.x;
        acc0[1] += w0.x * a.y + w0.y * bb.y + w0.z * c.y + w0.w * d.y;
        acc0[2] += w0.x * a.z + w0.y * bb.z + w0.z * c.z + w0.w * d.z;
        acc0[3] += w0.x * a.w + w0.y * bb.w + w0.z * c.w + w0.w * d.w;
        acc1[0] += w1.x * a.x + w1.y * bb.x + w1.z * c.x + w1.w * d.x;
        acc1[1] += w1.x * a.y + w1.y * bb.y + w1.z * c.y + w1.w * d.y;
        acc1[2] += w1.x * a.z + w1.y * bb.z + w1.z * c.z + w1.w * d.z;
        acc1[3] += w1.x * a.w + w1.y * bb.w + w1.z * c.w + w1.w * d.w;
    }
#pragma unroll
    for (int b = 0; b < B; b++) {
#pragma unroll
        for (int o = 16; o; o >>= 1) {
            acc0[b] += __shfl_xor_sync(0xffffffffu, acc0[b], o);
            acc1[b] += __shfl_xor_sync(0xffffffffu, acc1[b], o);
        }
    }
    if (lane == 0) {
#pragma unroll
        for (int b = 0; b < B; b++) {
            g_q[b * (NH * QD) + row] = acc0[b];
            g_q[b * (NH * QD) + row + 1] = acc1[b];
        }
    }
}

// ------------- kernel 4: q_abs[b,h,:] = q_nope[b,h,:] @ W_uk[h]  + rope(q_pe) -------------
// grid (NH, 4): (head, col quarter of 32 float4). block 256 = 32 float4-cols x 8 d-octiles.
__global__ void __launch_bounds__(256) k_absorb(const float* __restrict__ wkvb) {
    int h = blockIdx.x, zz = blockIdx.y;
    int t = threadIdx.x;
    int tx = t & 31, ty = t >> 5;
    int col4 = zz * 32 + tx;           // float4 column in [0,128)
    __shared__ float qn[B * NOPE];     // [b][d]
    __shared__ float4 red[8][32][B];   // 16 KB
    for (int idx = t; idx < B * NOPE; idx += 256) {
        int b = idx >> 7, d = idx & 127;
        qn[idx] = g_q[b * (NH * QD) + h * QD + d];
    }
    __syncthreads();
    const float4* w4 = reinterpret_cast<const float4*>(wkvb) + (size_t)h * 256 * 128;
    float4 acc[B];
#pragma unroll
    for (int b = 0; b < B; b++) acc[b] = make_float4(0.f, 0.f, 0.f, 0.f);
#pragma unroll
    for (int d = 0; d < 16; d++) {
        float4 w = w4[(size_t)(ty * 16 + d) * 128 + col4];
#pragma unroll
        for (int b = 0; b < B; b++) {
            float q = qn[b * NOPE + ty * 16 + d];
            acc[b].x += q * w.x; acc[b].y += q * w.y;
            acc[b].z += q * w.z; acc[b].w += q * w.w;
        }
    }
#pragma unroll
    for (int b = 0; b < B; b++) red[ty][tx][b] = acc[b];
    __syncthreads();
    if (ty < 4) {
        int b = ty;
        float4 s = red[0][tx][b];
#pragma unroll
        for (int g = 1; g < 8; g++) {
            float4 r = red[g][tx][b];
            s.x += r.x; s.y += r.y; s.z += r.z; s.w += r.w;
        }
        *reinterpret_cast<float4*>(&g_qcat[((size_t)(b * NH) + h) * CAT + col4 * 4]) = s;
    }
    // rope q_pe at position kv_len-1 = 2047 (done once per head, by zz==3 block)
    if (zz == 3 && t < 128) {
        int b = t >> 5, j = t & 31;
        float inv = exp2f(-(float)j * (LOG2_10000 / 32.f));
        float s, cc;
        sincosf(2047.0f * inv, &s, &cc);
        float xr = g_q[b * (NH * QD) + h * QD + NOPE + 2 * j];
        float xi = g_q[b * (NH * QD) + h * QD + NOPE + 2 * j + 1];
        g_qcat[((size_t)(b * NH) + h) * CAT + 512 + 2 * j]     = xr * cc - xi * s;
        g_qcat[((size_t)(b * NH) + h) * CAT + 512 + 2 * j + 1] = xr * s + xi * cc;
    }
}

// ------------------- kernel 5: rope k_pe for all positions (fp32) -------------------
__global__ void __launch_bounds__(256) k_ropek(const float* __restrict__ kpe) {
    int idx = blockIdx.x * 256 + threadIdx.x;  // < B*KVLEN*32 = 262144
    int j = idx & 31;
    int k = (idx >> 5) & (KVLEN - 1);
    int b = idx >> 16;
    float inv = exp2f(-(float)j * (LOG2_10000 / 32.f));
    float s, c;
    sincosf((float)k * inv, &s, &c);
    size_t base = ((size_t)(b * KVLEN) + k) * PE + 2 * j;
    float2 x = *reinterpret_cast<const float2*>(&kpe[base]);
    float2 o;
    o.x = x.x * c - x.y * s;
    o.y = x.x * s + x.y * c;
    *reinterpret_cast<float2*>(&g_kpe[base]) = o;
}

// ------------------- kernel 6: scores = qcat @ [ckv|kpe]^T * scale  (tf32 mma) -----
// grid (32 ktiles of 64, B); block 256 = 8 warps (4 m-groups x 2 n-groups)
// block tile: 128h x 64k; K-dim CAT staged in 18 chunks of 32
__global__ void __launch_bounds__(256) k_scores(const float* __restrict__ ckv) {
    __shared__ uint32_t A_sh[128 * 36];  // qcat chunk [h][c], stride 36 (18 KB)
    __shared__ uint32_t B_sh[64 * 36];   // kv chunk [k][c], stride 36 (9 KB)
    int b = blockIdx.y, k0 = blockIdx.x * 64;
    int t = threadIdx.x, w = t >> 5, lane = t & 31;
    int mw = w & 3, nw = w >> 2;
    int lq = lane >> 2, lr = lane & 3;   // groupID, threadID_in_group
    float acc[2][4][4];
#pragma unroll
    for (int mt = 0; mt < 2; mt++)
#pragma unroll
        for (int nt = 0; nt < 4; nt++)
#pragma unroll
            for (int i = 0; i < 4; i++) acc[mt][nt][i] = 0.f;

    for (int cc0 = 0; cc0 < CAT; cc0 += 32) {
        // stage A: qcat[b][0:128][cc0:cc0+32] -> tf32
#pragma unroll
        for (int r = 0; r < 16; r++) {
            int idx = r * 256 + t;
            int h = idx >> 5, c = idx & 31;
            A_sh[h * 36 + c] = f2tf(g_qcat[((size_t)(b << 7) + h) * CAT + cc0 + c]);
        }
        // stage B: kv rows k0..k0+64, cols cc0..cc0+32
#pragma unroll
        for (int r = 0; r < 8; r++) {
            int idx = r * 256 + t;
            int k = idx >> 5, c = idx & 31;
            float v = (cc0 < 512)
                ? ckv[((size_t)(b * KVLEN) + k0 + k) * KVL + cc0 + c]
                : g_kpe[((size_t)(b * KVLEN) + k0 + k) * PE + (cc0 - 512) + c];
            B_sh[k * 36 + c] = f2tf(v);
        }
        __syncthreads();
#pragma unroll
        for (int ks = 0; ks < 4; ks++) {
            int c = ks * 8;
            uint32_t a[2][4];
#pragma unroll
            for (int mt = 0; mt < 2; mt++) {
                int m0 = mw * 32 + mt * 16;
                a[mt][0] = A_sh[(m0 + lq) * 36 + c + lr];
                a[mt][1] = A_sh[(m0 + 8 + lq) * 36 + c + lr];
                a[mt][2] = A_sh[(m0 + lq) * 36 + c + 4 + lr];
                a[mt][3] = A_sh[(m0 + 8 + lq) * 36 + c + 4 + lr];
            }
#pragma unroll
            for (int nt = 0; nt < 4; nt++) {
                int n0 = nw * 32 + nt * 8;
                uint32_t b0 = B_sh[(n0 + lq) * 36 + c + lr];
                uint32_t b1 = B_sh[(n0 + lq) * 36 + c + 4 + lr];
                mma_tf32(acc[0][nt], a[0][0], a[0][1], a[0][2], a[0][3], b0, b1);
                mma_tf32(acc[1][nt], a[1][0], a[1][1], a[1][2], a[1][3], b0, b1);
            }
        }
        __syncthreads();
    }
    // writeback scaled scores
#pragma unroll
    for (int mt = 0; mt < 2; mt++) {
#pragma unroll
        for (int nt = 0; nt < 4; nt++) {
            int m0 = mw * 32 + mt * 16;
            int n0 = nw * 32 + nt * 8;
            int row = m0 + lq;
            int col = k0 + n0 + 2 * lr;
            float* base0 = &g_scores[((size_t)(b << 7) + row) * KVLEN + col];
            *reinterpret_cast<float2*>(base0) =
                make_float2(acc[mt][nt][0] * SCALE, acc[mt][nt][1] * SCALE);
            float* base1 = &g_scores[((size_t)(b << 7) + row + 8) * KVLEN + col];
            *reinterpret_cast<float2*>(base1) =
                make_float2(acc[mt][nt][2] * SCALE, acc[mt][nt][3] * SCALE);
        }
    }
}

// ------------------- kernel 7: softmax over k (in place) -------------------
__global__ void __launch_bounds__(256) k_softmax() {
    int bh = blockIdx.x, t = threadIdx.x;
    float* row = g_scores + (size_t)bh * KVLEN;
    __shared__ float redm[8], reds[8];
    float m = -1e30f;
    for (int i = t; i < KVLEN; i += 256) m = fmaxf(m, row[i]);
#pragma unroll
    for (int o = 16; o; o >>= 1) m = fmaxf(m, __shfl_xor_sync(0xffffffffu, m, o));
    if ((t & 31) == 0) redm[t >> 5] = m;
    __syncthreads();
    m = redm[0];
#pragma unroll
    for (int w = 1; w < 8; w++) m = fmaxf(m, redm[w]);
    float s = 0.f;
    for (int i = t; i < KVLEN; i += 256) {
        float e = expf(row[i] - m);
        row[i] = e;
        s += e;
    }
#pragma unroll
    for (int o = 16; o; o >>= 1) s += __shfl_xor_sync(0xffffffffu, s, o);
    if ((t & 31) == 0) reds[t >> 5] = s;
    __syncthreads();
    float tot = 0.f;
#pragma unroll
    for (int w = 0; w < 8; w++) tot += reds[w];
    float inv = 1.0f / tot;
    for (int i = t; i < KVLEN; i += 256) row[i] *= inv;
}

// ------------------- kernel 8: o_c partials = attn @ ckv (tf32 mma, K-split) -----
// grid (4 ctiles of 128, 8 ksegs of 256, B); block 256 = 8 warps (4 m x 2 n)
// block tile: 128h x 128c; K staged in 8 chunks of 32
__global__ void __launch_bounds__(256) k_oc(const float* __restrict__ ckv) {
    __shared__ uint32_t A_sh[128 * 36];   // attn chunk [h][k], stride 36 (18 KB)
    __shared__ uint32_t B_sh[32 * 136];   // ckv chunk [k][c], stride 136 (17.4 KB)
    int b = blockIdx.z, ks = blockIdx.y, c0 = blockIdx.x * 128;
    int k0b = ks * 256;
    int t = threadIdx.x, w = t >> 5, lane = t & 31;
    int mw = w & 3, nw = w >> 2;
    int lq = lane >> 2, lr = lane & 3;
    float acc[2][8][4];
#pragma unroll
    for (int mt = 0; mt < 2; mt++)
#pragma unroll
        for (int nt = 0; nt < 8; nt++)
#pragma unroll
            for (int i = 0; i < 4; i++) acc[mt][nt][i] = 0.f;

    for (int kc0 = 0; kc0 < 256; kc0 += 32) {
        int k0 = k0b + kc0;
        // stage A: attn[b][0:128][k0:k0+32]
#pragma unroll
        for (int r = 0; r < 16; r++) {
            int idx = r * 256 + t;
            int h = idx >> 5, k = idx & 31;
            A_sh[h * 36 + k] = f2tf(g_scores[((size_t)(b << 7) + h) * KVLEN + k0 + k]);
        }
        // stage B: ckv[b][k0:k0+32][c0:c0+128]
#pragma unroll
        for (int r = 0; r < 16; r++) {
            int idx = r * 256 + t;
            int k = idx >> 7, c = idx & 127;
            B_sh[k * 136 + c] = f2tf(ckv[((size_t)(b * KVLEN) + k0 + k) * KVL + c0 + c]);
        }
        __syncthreads();
#pragma unroll
        for (int kk = 0; kk < 32; kk += 8) {
            uint32_t a[2][4];
#pragma unroll
            for (int mt = 0; mt < 2; mt++) {
                int m0 = mw * 32 + mt * 16;
                a[mt][0] = A_sh[(m0 + lq) * 36 + kk + lr];
                a[mt][1] = A_sh[(m0 + 8 + lq) * 36 + kk + lr];
                a[mt][2] = A_sh[(m0 + lq) * 36 + kk + 4 + lr];
                a[mt][3] = A_sh[(m0 + 8 + lq) * 36 + kk + 4 + lr];
            }
#pragma unroll
            for (int nt = 0; nt < 8; nt++) {
                int n0 = nw * 64 + nt * 8;
                uint32_t b0 = B_sh[(kk + lr) * 136 + n0 + lq];
                uint32_t b1 = B_sh[(kk + 4 + lr) * 136 + n0 + lq];
                mma_tf32(acc[0][nt], a[0][0], a[0][1], a[0][2], a[0][3], b0, b1);
                mma_tf32(acc[1][nt], a[1][0], a[1][1], a[1][2], a[1][3], b0, b1);
            }
        }
        __syncthreads();
    }
    float* dst = g_ocp + (size_t)ks * (B * NH * KVL);
#pragma unroll
    for (int mt = 0; mt < 2; mt++) {
#pragma unroll
        for (int nt = 0; nt < 8; nt++) {
            int m0 = mw * 32 + mt * 16;
            int n0 = nw * 64 + nt * 8;
            int row = m0 + lq;
            int col = c0 + n0 + 2 * lr;
            *reinterpret_cast<float2*>(&dst[((size_t)(b << 7) + row) * KVL + col]) =
                make_float2(acc[mt][nt][0], acc[mt][nt][1]);
            *reinterpret_cast<float2*>(&dst[((size_t)(b << 7) + row + 8) * KVL + col]) =
                make_float2(acc[mt][nt][2], acc[mt][nt][3]);
        }
    }
}

// ------------------- kernel 9: reduce K-split partials -------------------
__global__ void __launch_bounds__(256) k_ocred() {
    int i = blockIdx.x * 256 + threadIdx.x;  // < B*NH*KVL = 262144
    float s = 0.f;
#pragma unroll
    for (int p = 0; p < OCP_SEG; p++) s += g_ocp[(size_t)p * (B * NH * KVL) + i];
    g_oc[i] = s;
}

// ------------------- kernel 10: out_v[b,h,:] = o_c[b,h,:] @ W_uv[h]^T -------------------
// grid NH*4: (h, dv-quarter of 32); warp computes 4 rows
__global__ void __launch_bounds__(256) k_outv(const float* __restrict__ wkvb) {
    int h = blockIdx.x >> 2, q = blockIdx.x & 3;
    int t = threadIdx.x;
    __shared__ __align__(16) float sh[KVL * B];  // [c][b], 8 KB
    for (int idx = t; idx < KVL * B; idx += 256) {
        int b = idx >> 9, c = idx & 511;
        sh[c * 4 + b] = g_oc[((size_t)(b << 7) + h) * KVL + c];
    }
    __syncthreads();
    int warp = t >> 5, lane = t & 31;
    const float4* sh4 = reinterpret_cast<const float4*>(sh);
    for (int r = 0; r < 4; r++) {
        int dv = q * 32 + warp * 4 + r;
        const float4* w4 = reinterpret_cast<const float4*>(wkvb + ((size_t)(h * 256 + 128 + dv)) * KVL);
        float acc[4] = {0.f, 0.f, 0.f, 0.f};
#pragma unroll
        for (int t4 = lane; t4 < 128; t4 += 32) {
            float4 w = w4[t4];
            float4 o0 = sh4[t4 * 4 + 0], o1 = sh4[t4 * 4 + 1];
            float4 o2 = sh4[t4 * 4 + 2], o3 = sh4[t4 * 4 + 3];
            acc[0] += w.x * o0.x + w.y * o1.x + w.z * o2.x + w.w * o3.x;
            acc[1] += w.x * o0.y + w.y * o1.y + w.z * o2.y + w.w * o3.y;
            acc[2] += w.x * o0.z + w.y * o1.z + w.z * o2.z + w.w * o3.z;
            acc[3] += w.x * o0.w + w.y * o1.w + w.z * o2.w + w.w * o3.w;
        }
#pragma unroll
        for (int b = 0; b < B; b++)
#pragma unroll
            for (int o = 16; o; o >>= 1) acc[b] += __shfl_xor_sync(0xffffffffu, acc[b], o);
        if (lane == 0)
            *reinterpret_cast<float4*>(&g_outvt[(h * VD + dv) * 4]) =
                make_float4(acc[0], acc[1], acc[2], acc[3]);
    }
}

// ------------------- kernel 11: final GEVM partials (split-K, warp = 2 rows) -----
// grid (HID/16, FCH); block 256; warp handles 2 rows sharing smem reads
__global__ void __launch_bounds__(256) k_final(const float* __restrict__ wo) {
    __shared__ float sv[B][2048];  // 32 KB: ov chunk as 4 batch planes
    int j0 = blockIdx.x * 16;
    int c0 = blockIdx.y * 2048;    // i offset of this chunk
    int t = threadIdx.x;
    const float4* ov4 = reinterpret_cast<const float4*>(g_outvt);
    for (int li = t; li < 2048; li += 256) {
        float4 v = ov4[c0 + li];   // all 4 batches for element c0+li
        sv[0][li] = v.x; sv[1][li] = v.y; sv[2][li] = v.z; sv[3][li] = v.w;
    }
    __syncthreads();
    int warp = t >> 5, lane = t & 31;
    int j = j0 + warp * 2;
    const float4* wjA = reinterpret_cast<const float4*>(wo + (size_t)j * (NH * VD)) + (c0 >> 2);
    const float4* wjB = reinterpret_cast<const float4*>(wo + (size_t)(j + 1) * (NH * VD)) + (c0 >> 2);
    float a0 = 0.f, a1 = 0.f, a2 = 0.f, a3 = 0.f;
    float b0 = 0.f, b1 = 0.f, b2 = 0.f, b3 = 0.f;
#pragma unroll
    for (int r = 0; r < 16; r++) {
        int l4 = lane + 32 * r;    // contiguous across lanes -> conflict-free LDS.128
        float4 wA = wjA[l4];
        float4 wB = wjB[l4];
        float4 s0 = *reinterpret_cast<const float4*>(&sv[0][l4 * 4]);
        float4 s1 = *reinterpret_cast<const float4*>(&sv[1][l4 * 4]);
        float4 s2 = *reinterpret_cast<const float4*>(&sv[2][l4 * 4]);
        float4 s3 = *reinterpret_cast<const float4*>(&sv[3][l4 * 4]);
        a0 += wA.x * s0.x + wA.y * s0.y + wA.z * s0.z + wA.w * s0.w;
        a1 += wA.x * s1.x + wA.y * s1.y + wA.z * s1.z + wA.w * s1.w;
        a2 += wA.x * s2.x + wA.y * s2.y + wA.z * s2.z + wA.w * s2.w;
        a3 += wA.x * s3.x + wA.y * s3.y + wA.z * s3.z + wA.w * s3.w;
        b0 += wB.x * s0.x + wB.y * s0.y + wB.z * s0.z + wB.w * s0.w;
        b1 += wB.x * s1.x + wB.y * s1.y + wB.z * s1.z + wB.w * s1.w;
        b2 += wB.x * s2.x + wB.y * s2.y + wB.z * s2.z + wB.w * s2.w;
        b3 += wB.x * s3.x + wB.y * s3.y + wB.z * s3.z + wB.w * s3.w;
    }
#pragma unroll
    for (int o = 16; o; o >>= 1) {
        a0 += __shfl_xor_sync(0xffffffffu, a0, o);
        a1 += __shfl_xor_sync(0xffffffffu, a1, o);
        a2 += __shfl_xor_sync(0xffffffffu, a2, o);
        a3 += __shfl_xor_sync(0xffffffffu, a3, o);
        b0 += __shfl_xor_sync(0xffffffffu, b0, o);
        b1 += __shfl_xor_sync(0xffffffffu, b1, o);
        b2 += __shfl_xor_sync(0xffffffffu, b2, o);
        b3 += __shfl_xor_sync(0xffffffffu, b3, o);
    }
    if (lane == 0) {
        size_t base = (size_t)blockIdx.y * (B * HID) + j;
        g_finp[base + 0 * HID] = a0;
        g_finp[base + 1 * HID] = a1;
        g_finp[base + 2 * HID] = a2;
        g_finp[base + 3 * HID] = a3;
        g_finp[base + 0 * HID + 1] = b0;
        g_finp[base + 1 * HID + 1] = b1;
        g_finp[base + 2 * HID + 1] = b2;
        g_finp[base + 3 * HID + 1] = b3;
    }
}

// ------------------- kernel 12: reduce final partials -------------------
__global__ void __launch_bounds__(256) k_fred(float* __restrict__ out) {
    int i = blockIdx.x * 256 + threadIdx.x;  // < B*HID = 20480
    float s = 0.f;
#pragma unroll
    for (int ch = 0; ch < FCH; ch++) s += g_finp[ch * (B * HID) + i];
    out[i] = s;
}

// ------------------- launch -------------------
extern "C" void kernel_launch(void* const* d_in, const int* in_sizes, int n_in,
                              void* d_out, int out_size) {
    const float* hidden = (const float*)d_in[0];
    const float* ckv    = (const float*)d_in[1];
    const float* kpe    = (const float*)d_in[2];
    const float* wqa    = (const float*)d_in[3];
    const float* wln    = (const float*)d_in[4];
    const float* wqb    = (const float*)d_in[5];
    const float* wkvb   = (const float*)d_in[6];
    const float* wo     = (const float*)d_in[7];
    float* out = (float*)d_out;

    k_qa<<<dim3(QLORA / 8, 2), 256>>>(hidden, wqa);
    k_rms<<<B, 256>>>(wln);
    k_qb<<<(NH * QD) / 16, 256>>>(wqb);
    k_absorb<<<dim3(NH, 4), 256>>>(wkvb);
    k_ropek<<<(B * KVLEN * 32) / 256, 256>>>(kpe);
    k_scores<<<dim3(KVLEN / 64, B), 256>>>(ckv);
    k_softmax<<<B * NH, 256>>>();
    k_oc<<<dim3(KVL / 128, OCP_SEG, B), 256>>>(ckv);
    k_ocred<<<(B * NH * KVL) / 256, 256>>>();
    k_outv<<<NH * 4, 256>>>(wkvb);
    k_final<<<dim3(HID / 16, FCH), 256>>>(wo);
    k_fred<<<(B * HID) / 256, 256>>>(out);
}